// round 11
// baseline (speedup 1.0000x reference)
#include <cuda_runtime.h>
#include <cstdint>

#define LL   2
#define TT   512
#define BB   128
#define HH   256
#define CLSZ 8
#define NCL  16
#define NTHR 512

// ---------------- smem layout (float indices) ----------------
#define OFF_U    0          // [128 col][260 pad h]         33280
#define OFF_HB   33280      // [256 h][8 b]                  2048
#define OFF_OUT  35328      // [2 parity][32 k][8 b]          512
#define OFF_PAR  35840      // [4 kq][8 b][128 col]          4096
#define OFF_WX   39936      // [128 col][4 f]                 512
#define OFF_WB   40448      // [128 col]                      128
#define OFF_FW   40576      // [256 k][4 f]                  1024
#define OFF_FB   41600      // [4]                              4
#define OFF_FLAG 41604      // [8] int step flags              8
#define SMEM_FLOATS 41612
#define SMEM_BYTES (SMEM_FLOATS * 4)

// layer-1 output scratch, TRANSPOSED: [B][T][4]
__device__ float g_y1[BB * TT * 4];

typedef unsigned long long ull;

__device__ __forceinline__ uint32_t smem_u32(const void* p) {
    uint32_t a;
    asm("{ .reg .u64 t; cvta.to.shared.u64 t, %1; cvt.u32.u64 %0, t; }"
        : "=r"(a) : "l"(p));
    return a;
}
__device__ __forceinline__ void cluster_sync() {
    asm volatile("barrier.cluster.arrive.aligned;" ::: "memory");
    asm volatile("barrier.cluster.wait.aligned;" ::: "memory");
}
__device__ __forceinline__ ull pack2(float a, float b) {
    ull r; asm("mov.b64 %0, {%1, %2};" : "=l"(r) : "f"(a), "f"(b)); return r;
}
__device__ __forceinline__ float2 unpack2(ull v) {
    float2 r; asm("mov.b64 {%0, %1}, %2;" : "=f"(r.x), "=f"(r.y) : "l"(v)); return r;
}
__device__ __forceinline__ ull ffma2(ull a, ull b, ull c) {
    ull d; asm("fma.rn.f32x2 %0, %1, %2, %3;" : "=l"(d) : "l"(a), "l"(b), "l"(c)); return d;
}
__device__ __forceinline__ float fsig(float x) {
    float e, r;
    asm("ex2.approx.f32 %0, %1;" : "=f"(e) : "f"(x * -1.4426950408889634f));
    asm("rcp.approx.f32 %0, %1;" : "=f"(r) : "f"(1.0f + e));
    return r;
}
__device__ __forceinline__ float ftanh(float x) {
    float e, r;
    asm("ex2.approx.f32 %0, %1;" : "=f"(e) : "f"(x * -2.8853900817779268f));
    asm("rcp.approx.f32 %0, %1;" : "=f"(r) : "f"(1.0f + e));
    return __fmaf_rn(2.0f, r, -1.0f);
}
// spin with backoff until local flag word >= target.
// Called by at most 1-2 lanes per warp: keeps the SMEM port free so the
// incoming st.shared::cluster flag stores can actually land.
__device__ __forceinline__ void flag_spin(uint32_t fa, int target) {
    int v;
    asm volatile("ld.volatile.shared.b32 %0, [%1];" : "=r"(v) : "r"(fa));
    while (v < target) {
        asm volatile("nanosleep.u32 64;");
        asm volatile("ld.volatile.shared.b32 %0, [%1];" : "=r"(v) : "r"(fa));
    }
}

#define QNEG_MASK 0x284E

__global__ void __launch_bounds__(NTHR, 1) __cluster_dims__(CLSZ, 1, 1)
qlstm_kernel(const float* __restrict__ x,
             const float* __restrict__ Wxr, const float* __restrict__ Wxi,
             const float* __restrict__ Wxj, const float* __restrict__ Wxk,
             const float* __restrict__ Wxb,
             const float* __restrict__ Ur,  const float* __restrict__ Ui,
             const float* __restrict__ Uj,  const float* __restrict__ Uk,
             const float* __restrict__ fcw, const float* __restrict__ fcb,
             float* __restrict__ out)
{
    extern __shared__ float sm[];
    float* sU   = sm + OFF_U;
    float* sHB  = sm + OFF_HB;
    float* sOut = sm + OFF_OUT;
    float* sPar = sm + OFF_PAR;
    float* sWx  = sm + OFF_WX;
    float* sWb  = sm + OFF_WB;
    float* sFW  = sm + OFF_FW;
    float* sFB  = sm + OFF_FB;

    const int tid  = threadIdx.x;
    const int lane = tid & 31;
    const int wid  = tid >> 5;
    const int col  = tid & 127;        // GEMM column
    const int kq   = tid >> 7;         // split-K quarter
    const int r    = blockIdx.x & 7;
    const int cid  = blockIdx.x >> 3;
    const int k    = lane;             // activation k (tid<128)
    const int b0   = wid * 2;          // activation batch pair (warps 0..3)
    const int b1   = b0 + 1;
    const uint32_t sbase = smem_u32(sm);

    // pull-plan: warp-uniform source ranks j0, j0+4; per-thread b64 offset
    const int poff = tid & 127;        // b64 index within slice
    const int j0   = tid >> 7;         // 0..3 (uniform within warp)
    const int j1   = j0 + 4;
    const uint32_t flag0 = sbase + (OFF_FLAG + j0) * 4;
    const uint32_t flag1 = sbase + (OFF_FLAG + j1) * 4;

    // ---- one-time init ----
    if (tid < 8) ((int*)(sm + OFF_FLAG))[tid] = 0;
    __syncthreads();
    cluster_sync();    // flags zeroed cluster-wide before any flag can arrive

    float2 creg;

    for (int l = 0; l < LL; l++) {
        __syncthreads();  // previous-phase readers done (incl. post-loop y-warp)

        // ---- gather U slice transposed+padded: sU[col*260 + h] ----
        for (int idx = tid; idx < 4 * 256 * 32; idx += NTHR) {
            int g   = idx >> 13;
            int rem = idx & 8191;
            int h   = rem >> 5;
            int kl  = rem & 31;
            int kg  = r * 32 + kl;
            int hb  = h >> 6, n = h & 63;
            int cb  = kg >> 6, m = kg & 63;
            int sel = hb ^ cb;
            float sgn = ((QNEG_MASK >> (cb * 4 + hb)) & 1) ? -1.0f : 1.0f;
            const float* cp = (sel == 0) ? Ur : (sel == 1) ? Ui : (sel == 2) ? Uj : Uk;
            sU[(g * 32 + kl) * 260 + h] =
                sgn * __ldg(&cp[((l * 4 + g) * 64 + n) * 64 + m]);
        }
        for (int idx = tid; idx < 512; idx += NTHR) {
            int g  = idx >> 7;
            int f  = (idx >> 5) & 3;
            int kl = idx & 31;
            int kg = r * 32 + kl;
            int cb = kg >> 6, m = kg & 63;
            int sel = f ^ cb;
            float sgn = ((QNEG_MASK >> (cb * 4 + f)) & 1) ? -1.0f : 1.0f;
            const float* cp = (sel == 0) ? Wxr : (sel == 1) ? Wxi : (sel == 2) ? Wxj : Wxk;
            sWx[(g * 32 + kl) * 4 + f] = sgn * __ldg(&cp[(l * 4 + g) * 64 + m]);
        }
        for (int idx = tid; idx < 128; idx += NTHR) {
            int g = idx >> 5, kl = idx & 31;
            sWb[idx] = Wxb[(l * 4 + g) * 256 + r * 32 + kl];
        }
        for (int idx = tid; idx < 1024; idx += NTHR)
            sFW[idx] = fcw[l * 1024 + idx];            // [256 k][4 f]
        if (tid < 4) sFB[tid] = fcb[l * 4 + tid];
        // zero h buffer (h_0 = 0); purely local
        for (int i = tid; i < 256 * 8; i += NTHR) sHB[i] = 0.0f;
        creg = make_float2(0.0f, 0.0f);
        __syncthreads();

        const float4* xp = (const float4*)((l == 0) ? x : g_y1);  // [B][T][4]

        for (int t = 0; t < TT; t++) {
            const float* hbc = sHB + kq * 512;         // kq*64 h × 8 b
            const float* up  = sU + col * 260 + kq * 64;

            // ---- y-warp: y_{t-1} = norm(fco(h_t)) (layer 0; overlaps GEMM) ----
            if (l == 0 && wid == 15 && t > 0) {
                float s0 = 0.f, s1 = 0.f, s2 = 0.f, s3 = 0.f;
#pragma unroll
                for (int i = 0; i < 8; i++) {
                    int kk = lane + i * 32;
                    float hv = sHB[kk * 8 + r];
                    float4 fw = *(const float4*)&sFW[kk * 4];
                    s0 += hv * fw.x; s1 += hv * fw.y;
                    s2 += hv * fw.z; s3 += hv * fw.w;
                }
#pragma unroll
                for (int m = 16; m >= 1; m >>= 1) {
                    s0 += __shfl_xor_sync(0xffffffffu, s0, m);
                    s1 += __shfl_xor_sync(0xffffffffu, s1, m);
                    s2 += __shfl_xor_sync(0xffffffffu, s2, m);
                    s3 += __shfl_xor_sync(0xffffffffu, s3, m);
                }
                if (lane == 0) {
                    s0 += sFB[0]; s1 += sFB[1]; s2 += sFB[2]; s3 += sFB[3];
                    float nn = s0 * s0 + s1 * s1 + s2 * s2 + s3 * s3;
                    float iv = 1.0f / fmaxf(sqrtf(nn), 1e-12f);
                    ((float4*)g_y1)[(cid * 8 + r) * TT + (t - 1)] =
                        make_float4(s0 * iv, s1 * iv, s2 * iv, s3 * iv);
                }
            }

            // ---- acc init: kq==0 adds bias + x_t @ Wx ----
            ull A0, A1, A2, A3;
            if (kq == 0) {
                float4 wxc = *(const float4*)&sWx[col * 4];
                float  wbc = sWb[col];
                float acc[8];
#pragma unroll
                for (int j = 0; j < 8; j++) {
                    float4 xv = __ldg(&xp[(cid * 8 + j) * TT + t]);
                    acc[j] = wbc + xv.x * wxc.x + xv.y * wxc.y
                                 + xv.z * wxc.z + xv.w * wxc.w;
                }
                A0 = pack2(acc[0], acc[1]); A1 = pack2(acc[2], acc[3]);
                A2 = pack2(acc[4], acc[5]); A3 = pack2(acc[6], acc[7]);
            } else {
                A0 = A1 = A2 = A3 = 0ull;
            }

            // ---- GEMM quarter: 64 h × 8 batches ----
#pragma unroll
            for (int hh = 0; hh < 64; hh += 4) {
                float4 u4 = *(const float4*)(up + hh);
                const float* hp = hbc + hh * 8;
                {
                    ull uu = pack2(u4.x, u4.x);
                    ulonglong2 a = *(const ulonglong2*)(hp);
                    ulonglong2 b = *(const ulonglong2*)(hp + 4);
                    A0 = ffma2(a.x, uu, A0); A1 = ffma2(a.y, uu, A1);
                    A2 = ffma2(b.x, uu, A2); A3 = ffma2(b.y, uu, A3);
                }
                {
                    ull uu = pack2(u4.y, u4.y);
                    ulonglong2 a = *(const ulonglong2*)(hp + 8);
                    ulonglong2 b = *(const ulonglong2*)(hp + 12);
                    A0 = ffma2(a.x, uu, A0); A1 = ffma2(a.y, uu, A1);
                    A2 = ffma2(b.x, uu, A2); A3 = ffma2(b.y, uu, A3);
                }
                {
                    ull uu = pack2(u4.z, u4.z);
                    ulonglong2 a = *(const ulonglong2*)(hp + 16);
                    ulonglong2 b = *(const ulonglong2*)(hp + 20);
                    A0 = ffma2(a.x, uu, A0); A1 = ffma2(a.y, uu, A1);
                    A2 = ffma2(b.x, uu, A2); A3 = ffma2(b.y, uu, A3);
                }
                {
                    ull uu = pack2(u4.w, u4.w);
                    ulonglong2 a = *(const ulonglong2*)(hp + 24);
                    ulonglong2 b = *(const ulonglong2*)(hp + 28);
                    A0 = ffma2(a.x, uu, A0); A1 = ffma2(a.y, uu, A1);
                    A2 = ffma2(b.x, uu, A2); A3 = ffma2(b.y, uu, A3);
                }
            }

            // ---- write partials: sPar[kq][b][col] ----
            {
                float* pp = sPar + kq * 1024 + col;
                float2 v;
                v = unpack2(A0); pp[0 * 128] = v.x; pp[1 * 128] = v.y;
                v = unpack2(A1); pp[2 * 128] = v.x; pp[3 * 128] = v.y;
                v = unpack2(A2); pp[4 * 128] = v.x; pp[5 * 128] = v.y;
                v = unpack2(A3); pp[6 * 128] = v.x; pp[7 * 128] = v.y;
            }
            __syncthreads();

            // ---- combine + activations + LOCAL h store (tid<128) ----
            if (tid < 128) {
                float hn0, hn1;
#pragma unroll
                for (int bi = 0; bi < 2; bi++) {
                    const int b = bi ? b1 : b0;
                    const float* pb = sPar + b * 128 + k;
                    float pf = 0.f, pi = 0.f, po = 0.f, pc = 0.f;
#pragma unroll
                    for (int q = 0; q < 4; q++) {
                        const float* pq = pb + q * 1024;
                        pf += pq[0];
                        pi += pq[32];
                        po += pq[64];
                        pc += pq[96];
                    }
                    float ft = fsig(pf);
                    float it = fsig(pi);
                    float ot = fsig(po);
                    float ct = ftanh(pc);
                    float cold = bi ? creg.y : creg.x;
                    float c  = it * ct + ft * cold;
                    if (bi) creg.y = c; else creg.x = c;
                    float hn = ot * ftanh(c);
                    if (bi) hn1 = hn; else hn0 = hn;
                }
                *(ull*)(sOut + (t & 1) * 256 + k * 8 + b0) = pack2(hn0, hn1);
            }

            __syncthreads();   // drains sOut STS to SMEM (HW-native on BAR)

            // ---- publish: push step flag to all 8 ranks (monotonic, no ABA) ----
            const int gs = l * TT + t + 1;
            if (tid == 0) {
                uint32_t fa = sbase + (OFF_FLAG + r) * 4;
#pragma unroll
                for (int j = 0; j < CLSZ; j++) {
                    uint32_t ra;
                    asm("mapa.shared::cluster.u32 %0, %1, %2;"
                        : "=r"(ra) : "r"(fa), "r"(j));
                    asm volatile("st.shared::cluster.b32 [%0], %1;"
                                 :: "r"(ra), "r"(gs) : "memory");
                }
            }

            // ---- spin: ONLY lanes 0/1 of each warp poll (flags are
            //      warp-uniform); everyone else parks at syncwarp ----
            if (lane == 0) flag_spin(flag0, gs);
            if (lane == 1) flag_spin(flag1, gs);
            __syncwarp();

            // ---- pull both slices into local sHB ----
            {
                const uint32_t so = sbase + (OFF_OUT + (t & 1) * 256) * 4 + poff * 8;
                uint32_t ra; ull v;
                asm("mapa.shared::cluster.u32 %0, %1, %2;"
                    : "=r"(ra) : "r"(so), "r"(j0));
                asm volatile("ld.shared::cluster.b64 %0, [%1];"
                             : "=l"(v) : "r"(ra) : "memory");
                *(ull*)(sHB + j0 * 256 + poff * 2) = v;
                asm("mapa.shared::cluster.u32 %0, %1, %2;"
                    : "=r"(ra) : "r"(so), "r"(j1));
                asm volatile("ld.shared::cluster.b64 %0, [%1];"
                             : "=l"(v) : "r"(ra) : "memory");
                *(ull*)(sHB + j1 * 256 + poff * 2) = v;
            }
            __syncthreads();  // sHB = h_{t+1} complete
        } // t

        // ---- final y from h_T (both layers) ----
        if (wid == 15) {
            float s0 = 0.f, s1 = 0.f, s2 = 0.f, s3 = 0.f;
#pragma unroll
            for (int i = 0; i < 8; i++) {
                int kk = lane + i * 32;
                float hv = sHB[kk * 8 + r];
                float4 fw = *(const float4*)&sFW[kk * 4];
                s0 += hv * fw.x; s1 += hv * fw.y;
                s2 += hv * fw.z; s3 += hv * fw.w;
            }
#pragma unroll
            for (int m = 16; m >= 1; m >>= 1) {
                s0 += __shfl_xor_sync(0xffffffffu, s0, m);
                s1 += __shfl_xor_sync(0xffffffffu, s1, m);
                s2 += __shfl_xor_sync(0xffffffffu, s2, m);
                s3 += __shfl_xor_sync(0xffffffffu, s3, m);
            }
            if (lane == 0) {
                s0 += sFB[0]; s1 += sFB[1]; s2 += sFB[2]; s3 += sFB[3];
                float nn = s0 * s0 + s1 * s1 + s2 * s2 + s3 * s3;
                float iv = 1.0f / fmaxf(sqrtf(nn), 1e-12f);
                if (l == 0) {
                    ((float4*)g_y1)[(cid * 8 + r) * TT + (TT - 1)] =
                        make_float4(s0 * iv, s1 * iv, s2 * iv, s3 * iv);
                } else {
                    ((float4*)out)[cid * 8 + r] =
                        make_float4(s0 * iv, s1 * iv, s2 * iv, s3 * iv);
                }
            }
        }
    } // l

    cluster_sync();   // no CTA exits while peers may still touch its SMEM
}

extern "C" void kernel_launch(void* const* d_in, const int* in_sizes, int n_in,
                              void* d_out, int out_size)
{
    (void)in_sizes; (void)n_in; (void)out_size;
    cudaFuncSetAttribute(qlstm_kernel,
                         cudaFuncAttributeMaxDynamicSharedMemorySize, SMEM_BYTES);
    qlstm_kernel<<<NCL * CLSZ, NTHR, SMEM_BYTES>>>(
        (const float*)d_in[0],
        (const float*)d_in[1], (const float*)d_in[2],
        (const float*)d_in[3], (const float*)d_in[4],
        (const float*)d_in[5],
        (const float*)d_in[6], (const float*)d_in[7],
        (const float*)d_in[8], (const float*)d_in[9],
        (const float*)d_in[10], (const float*)d_in[11],
        (float*)d_out);
}

// round 12
// speedup vs baseline: 2.5267x; 2.5267x over previous
#include <cuda_runtime.h>
#include <cstdint>

#define LL   2
#define TT   512
#define BB   128
#define HH   256
#define CLSZ 8
#define NCL  16
#define NTHR 512

// ---------------- smem layout (float indices) ----------------
#define OFF_U    0          // [128 col][260 pad h]  (tf32 bits) 33280
#define OFF_HB   33280      // [8 b][260 pad h]                   2080
#define OFF_OUT  35360      // [2 parity][8 b][32 h]               512
#define OFF_PRE2 35872      // [2 kh][128 col][9 pad b]           2304
#define OFF_WX   38176      // [128 col][4 f]                      512
#define OFF_WB   38688      // [128 col]                           128
#define OFF_FW   38816      // [256 k][4 f]                       1024
#define OFF_FB   39840      // [4]                                    4
#define OFF_FLAG 39844      // [8] int step flags                    8
#define SMEM_FLOATS 39852
#define SMEM_BYTES (SMEM_FLOATS * 4)

// layer-1 output scratch, TRANSPOSED: [B][T][4]
__device__ float g_y1[BB * TT * 4];

typedef unsigned long long ull;

__device__ __forceinline__ uint32_t smem_u32(const void* p) {
    uint32_t a;
    asm("{ .reg .u64 t; cvta.to.shared.u64 t, %1; cvt.u32.u64 %0, t; }"
        : "=r"(a) : "l"(p));
    return a;
}
__device__ __forceinline__ void cluster_sync() {
    asm volatile("barrier.cluster.arrive.aligned;" ::: "memory");
    asm volatile("barrier.cluster.wait.aligned;" ::: "memory");
}
__device__ __forceinline__ float fsig(float x) {
    float e, r;
    asm("ex2.approx.f32 %0, %1;" : "=f"(e) : "f"(x * -1.4426950408889634f));
    asm("rcp.approx.f32 %0, %1;" : "=f"(r) : "f"(1.0f + e));
    return r;
}
__device__ __forceinline__ float ftanh(float x) {
    float e, r;
    asm("ex2.approx.f32 %0, %1;" : "=f"(e) : "f"(x * -2.8853900817779268f));
    asm("rcp.approx.f32 %0, %1;" : "=f"(r) : "f"(1.0f + e));
    return __fmaf_rn(2.0f, r, -1.0f);
}
__device__ __forceinline__ uint32_t f2tf32(float x) {
    uint32_t u;
    asm("cvt.rna.tf32.f32 %0, %1;" : "=r"(u) : "f"(x));
    return u;
}
__device__ __forceinline__ void flag_spin(uint32_t fa, int target) {
    int v;
    do {
        asm volatile("ld.volatile.shared.b32 %0, [%1];" : "=r"(v) : "r"(fa));
    } while (v < target);
}
__device__ __forceinline__ void mma_tf32(float& d0, float& d1, float& d2, float& d3,
                                         uint32_t a0, uint32_t a1, uint32_t a2, uint32_t a3,
                                         uint32_t b0, uint32_t b1) {
    asm("mma.sync.aligned.m16n8k8.row.col.f32.tf32.tf32.f32 "
        "{%0,%1,%2,%3},{%4,%5,%6,%7},{%8,%9},{%0,%1,%2,%3};"
        : "+f"(d0), "+f"(d1), "+f"(d2), "+f"(d3)
        : "r"(a0), "r"(a1), "r"(a2), "r"(a3), "r"(b0), "r"(b1));
}

#define QNEG_MASK 0x284E

__global__ void __launch_bounds__(NTHR, 1) __cluster_dims__(CLSZ, 1, 1)
qlstm_kernel(const float* __restrict__ x,
             const float* __restrict__ Wxr, const float* __restrict__ Wxi,
             const float* __restrict__ Wxj, const float* __restrict__ Wxk,
             const float* __restrict__ Wxb,
             const float* __restrict__ Ur,  const float* __restrict__ Ui,
             const float* __restrict__ Uj,  const float* __restrict__ Uk,
             const float* __restrict__ fcw, const float* __restrict__ fcb,
             float* __restrict__ out)
{
    extern __shared__ float sm[];
    float* sU   = sm + OFF_U;
    float* sHB  = sm + OFF_HB;
    float* sOut = sm + OFF_OUT;
    float* sPre = sm + OFF_PRE2;
    float* sWx  = sm + OFF_WX;
    float* sWb  = sm + OFF_WB;
    float* sFW  = sm + OFF_FW;
    float* sFB  = sm + OFF_FB;

    const int tid  = threadIdx.x;
    const int lane = tid & 31;
    const int wid  = tid >> 5;
    const int r    = blockIdx.x & 7;
    const int cid  = blockIdx.x >> 3;
    const uint32_t sbase = smem_u32(sm);

    // mma role: warp = (col-tile ct 0..7, K-half kh 0..1)
    const int ct = wid & 7;
    const int kh = wid >> 3;
    const int mr = lane >> 2;      // fragment row group 0..7
    const int mc = lane & 3;       // fragment k/col group 0..3

    // act role (warps 0..3): cell (k=lane, batches b0,b1)
    const int k  = lane;
    const int b0 = wid * 2;
    const int b1 = b0 + 1;

    // pull role: 64 threads per source rank; each thread moves 16B
    const int pj = tid >> 6;           // source rank 0..7
    const int pb = (tid >> 3) & 7;     // batch 0..7
    const int pq = tid & 7;            // 16B chunk within 128B row-slice
    const uint32_t flagA = sbase + (OFF_FLAG + pj) * 4;

    // ---- one-time init ----
    if (tid < 8) ((int*)(sm + OFF_FLAG))[tid] = 0;
    __syncthreads();
    cluster_sync();

    float2 creg;

    for (int l = 0; l < LL; l++) {
        __syncthreads();  // previous-phase readers done

        // ---- gather U slice (tf32-rounded), layout sU[col][260 pad h] ----
        for (int idx = tid; idx < 4 * 256 * 32; idx += NTHR) {
            int g   = idx >> 13;
            int rem = idx & 8191;
            int h   = rem >> 5;
            int kl  = rem & 31;
            int kg  = r * 32 + kl;
            int hb  = h >> 6, n = h & 63;
            int cb  = kg >> 6, m = kg & 63;
            int sel = hb ^ cb;
            float sgn = ((QNEG_MASK >> (cb * 4 + hb)) & 1) ? -1.0f : 1.0f;
            const float* cp = (sel == 0) ? Ur : (sel == 1) ? Ui : (sel == 2) ? Uj : Uk;
            float v = sgn * __ldg(&cp[((l * 4 + g) * 64 + n) * 64 + m]);
            sU[(g * 32 + kl) * 260 + h] = __uint_as_float(f2tf32(v));
        }
        for (int idx = tid; idx < 512; idx += NTHR) {
            int g  = idx >> 7;
            int f  = (idx >> 5) & 3;
            int kl = idx & 31;
            int kg = r * 32 + kl;
            int cb = kg >> 6, m = kg & 63;
            int sel = f ^ cb;
            float sgn = ((QNEG_MASK >> (cb * 4 + f)) & 1) ? -1.0f : 1.0f;
            const float* cp = (sel == 0) ? Wxr : (sel == 1) ? Wxi : (sel == 2) ? Wxj : Wxk;
            sWx[(g * 32 + kl) * 4 + f] = sgn * __ldg(&cp[(l * 4 + g) * 64 + m]);
        }
        for (int idx = tid; idx < 128; idx += NTHR) {
            int g = idx >> 5, kl = idx & 31;
            sWb[idx] = Wxb[(l * 4 + g) * 256 + r * 32 + kl];
        }
        for (int idx = tid; idx < 1024; idx += NTHR)
            sFW[idx] = fcw[l * 1024 + idx];
        if (tid < 4) sFB[tid] = fcb[l * 4 + tid];
        // zero h buffer (h_0 = 0), incl padding
        for (int i = tid; i < 8 * 260; i += NTHR) sHB[i] = 0.0f;
        creg = make_float2(0.0f, 0.0f);
        __syncthreads();

        // ---- preload this warp's U A-fragments into registers (per layer) ----
        uint32_t Afr[16][4];
        {
            const int row0 = ct * 16 + mr;
            const int kb0  = kh * 128 + mc;
#pragma unroll
            for (int kt = 0; kt < 16; kt++) {
                int kb = kb0 + kt * 8;
                Afr[kt][0] = __float_as_uint(sU[row0 * 260 + kb]);
                Afr[kt][1] = __float_as_uint(sU[(row0 + 8) * 260 + kb]);
                Afr[kt][2] = __float_as_uint(sU[row0 * 260 + kb + 4]);
                Afr[kt][3] = __float_as_uint(sU[(row0 + 8) * 260 + kb + 4]);
            }
        }

        const float4* xp = (const float4*)((l == 0) ? x : g_y1);  // [B][T][4]

        for (int t = 0; t < TT; t++) {
            // ---- y-warp: y_{t-1} = norm(fco(h_t)) (layer 0; overlaps GEMM) ----
            if (l == 0 && wid == 15 && t > 0) {
                float s0 = 0.f, s1 = 0.f, s2 = 0.f, s3 = 0.f;
#pragma unroll
                for (int i = 0; i < 8; i++) {
                    int kk = lane + i * 32;
                    float hv = sHB[r * 260 + kk];
                    float4 fw = *(const float4*)&sFW[kk * 4];
                    s0 += hv * fw.x; s1 += hv * fw.y;
                    s2 += hv * fw.z; s3 += hv * fw.w;
                }
#pragma unroll
                for (int m = 16; m >= 1; m >>= 1) {
                    s0 += __shfl_xor_sync(0xffffffffu, s0, m);
                    s1 += __shfl_xor_sync(0xffffffffu, s1, m);
                    s2 += __shfl_xor_sync(0xffffffffu, s2, m);
                    s3 += __shfl_xor_sync(0xffffffffu, s3, m);
                }
                if (lane == 0) {
                    s0 += sFB[0]; s1 += sFB[1]; s2 += sFB[2]; s3 += sFB[3];
                    float nn = s0 * s0 + s1 * s1 + s2 * s2 + s3 * s3;
                    float iv = 1.0f / fmaxf(sqrtf(nn), 1e-12f);
                    ((float4*)g_y1)[(cid * 8 + r) * TT + (t - 1)] =
                        make_float4(s0 * iv, s1 * iv, s2 * iv, s3 * iv);
                }
            }

            // ---- tensor GEMM: D[16c x 8b] += U^T tile @ h ----
            {
                float dA0 = 0.f, dA1 = 0.f, dA2 = 0.f, dA3 = 0.f;
                float dB0 = 0.f, dB1 = 0.f, dB2 = 0.f, dB3 = 0.f;
                const float* bp = sHB + mr * 260 + kh * 128 + mc;
#pragma unroll
                for (int kt = 0; kt < 8; kt++) {
                    uint32_t bb0 = __float_as_uint(bp[kt * 8]);
                    uint32_t bb1 = __float_as_uint(bp[kt * 8 + 4]);
                    mma_tf32(dA0, dA1, dA2, dA3,
                             Afr[kt][0], Afr[kt][1], Afr[kt][2], Afr[kt][3], bb0, bb1);
                }
#pragma unroll
                for (int kt = 8; kt < 16; kt++) {
                    uint32_t bb0 = __float_as_uint(bp[kt * 8]);
                    uint32_t bb1 = __float_as_uint(bp[kt * 8 + 4]);
                    mma_tf32(dB0, dB1, dB2, dB3,
                             Afr[kt][0], Afr[kt][1], Afr[kt][2], Afr[kt][3], bb0, bb1);
                }
                // store D to sPre[kh][col][9]: d0,d1 -> (row, b=2mc,2mc+1); d2,d3 -> row+8
                const int colA = ct * 16 + mr;
                const int bb   = mc * 2;
                float* p0 = sPre + kh * 1152 + colA * 9 + bb;
                float* p1 = sPre + kh * 1152 + (colA + 8) * 9 + bb;
                p0[0] = dA0 + dB0; p0[1] = dA1 + dB1;
                p1[0] = dA2 + dB2; p1[1] = dA3 + dB3;
            }
            __syncthreads();

            // ---- activations: cell update on warps 0..3 ----
            if (tid < 128) {
                float4 xv0 = __ldg(&xp[(cid * 8 + b0) * TT + t]);
                float4 xv1 = __ldg(&xp[(cid * 8 + b1) * TT + t]);
                float pre0[4], pre1[4];
#pragma unroll
                for (int g = 0; g < 4; g++) {
                    int col = g * 32 + k;
                    float4 wx = *(const float4*)&sWx[col * 4];
                    float wb  = sWb[col];
                    float base0 = sPre[col * 9 + b0] + sPre[1152 + col * 9 + b0];
                    float base1 = sPre[col * 9 + b1] + sPre[1152 + col * 9 + b1];
                    pre0[g] = base0 + wb + xv0.x * wx.x + xv0.y * wx.y
                                         + xv0.z * wx.z + xv0.w * wx.w;
                    pre1[g] = base1 + wb + xv1.x * wx.x + xv1.y * wx.y
                                         + xv1.z * wx.z + xv1.w * wx.w;
                }
                {
                    float ft = fsig(pre0[0]), it = fsig(pre0[1]);
                    float ot = fsig(pre0[2]), cc = ftanh(pre0[3]);
                    float c = it * cc + ft * creg.x;
                    creg.x = c;
                    float hn = ot * ftanh(c);
                    sOut[(t & 1) * 256 + b0 * 32 + k] = __uint_as_float(f2tf32(hn));
                }
                {
                    float ft = fsig(pre1[0]), it = fsig(pre1[1]);
                    float ot = fsig(pre1[2]), cc = ftanh(pre1[3]);
                    float c = it * cc + ft * creg.y;
                    creg.y = c;
                    float hn = ot * ftanh(c);
                    sOut[(t & 1) * 256 + b1 * 32 + k] = __uint_as_float(f2tf32(hn));
                }
            }
            __syncthreads();   // sOut committed (BAR drains STS)

            // ---- publish flag to all 8 ranks ----
            const int gs = l * TT + t + 1;
            if (tid == 0) {
                uint32_t fa = sbase + (OFF_FLAG + r) * 4;
#pragma unroll
                for (int j = 0; j < CLSZ; j++) {
                    uint32_t ra;
                    asm("mapa.shared::cluster.u32 %0, %1, %2;"
                        : "=r"(ra) : "r"(fa), "r"(j));
                    asm volatile("st.shared::cluster.b32 [%0], %1;"
                                 :: "r"(ra), "r"(gs) : "memory");
                }
            }

            // ---- spin (lane0 per warp; source rank is warp-uniform) & pull ----
            if (lane == 0) flag_spin(flagA, gs);
            __syncwarp();
            {
                const uint32_t so = sbase +
                    (OFF_OUT + (t & 1) * 256 + pb * 32 + pq * 4) * 4;
                uint32_t ra;
                asm("mapa.shared::cluster.u32 %0, %1, %2;"
                    : "=r"(ra) : "r"(so), "r"(pj));
                ull v0, v1;
                asm volatile("ld.shared::cluster.v2.u64 {%0,%1}, [%2];"
                             : "=l"(v0), "=l"(v1) : "r"(ra) : "memory");
                float* dst = sHB + pb * 260 + pj * 32 + pq * 4;
                asm volatile("st.shared.v2.u64 [%0], {%1,%2};"
                             :: "r"(sbase + (uint32_t)(OFF_HB + pb * 260 + pj * 32 + pq * 4) * 4),
                                "l"(v0), "l"(v1) : "memory");
                (void)dst;
            }
            __syncthreads();  // sHB = h_{t+1} complete
        } // t

        // ---- final y from h_T ----
        if (wid == 15) {
            float s0 = 0.f, s1 = 0.f, s2 = 0.f, s3 = 0.f;
#pragma unroll
            for (int i = 0; i < 8; i++) {
                int kk = lane + i * 32;
                float hv = sHB[r * 260 + kk];
                float4 fw = *(const float4*)&sFW[kk * 4];
                s0 += hv * fw.x; s1 += hv * fw.y;
                s2 += hv * fw.z; s3 += hv * fw.w;
            }
#pragma unroll
            for (int m = 16; m >= 1; m >>= 1) {
                s0 += __shfl_xor_sync(0xffffffffu, s0, m);
                s1 += __shfl_xor_sync(0xffffffffu, s1, m);
                s2 += __shfl_xor_sync(0xffffffffu, s2, m);
                s3 += __shfl_xor_sync(0xffffffffu, s3, m);
            }
            if (lane == 0) {
                s0 += sFB[0]; s1 += sFB[1]; s2 += sFB[2]; s3 += sFB[3];
                float nn = s0 * s0 + s1 * s1 + s2 * s2 + s3 * s3;
                float iv = 1.0f / fmaxf(sqrtf(nn), 1e-12f);
                if (l == 0) {
                    ((float4*)g_y1)[(cid * 8 + r) * TT + (TT - 1)] =
                        make_float4(s0 * iv, s1 * iv, s2 * iv, s3 * iv);
                } else {
                    ((float4*)out)[cid * 8 + r] =
                        make_float4(s0 * iv, s1 * iv, s2 * iv, s3 * iv);
                }
            }
        }
    } // l

    cluster_sync();   // no CTA exits while peers may still touch its SMEM
}

extern "C" void kernel_launch(void* const* d_in, const int* in_sizes, int n_in,
                              void* d_out, int out_size)
{
    (void)in_sizes; (void)n_in; (void)out_size;
    cudaFuncSetAttribute(qlstm_kernel,
                         cudaFuncAttributeMaxDynamicSharedMemorySize, SMEM_BYTES);
    qlstm_kernel<<<NCL * CLSZ, NTHR, SMEM_BYTES>>>(
        (const float*)d_in[0],
        (const float*)d_in[1], (const float*)d_in[2],
        (const float*)d_in[3], (const float*)d_in[4],
        (const float*)d_in[5],
        (const float*)d_in[6], (const float*)d_in[7],
        (const float*)d_in[8], (const float*)d_in[9],
        (const float*)d_in[10], (const float*)d_in[11],
        (float*)d_out);
}